// round 1
// baseline (speedup 1.0000x reference)
#include <cuda_runtime.h>

// TorchGrouper: voxel-neighborhood feature gather + transpose.
// Output layout (float32): [C*G*K] sampled_features [C,G,K],
// then [4*G*K] gpf, then [G] empty_mask (1.0/0.0).

#define NN 2
#define ZDIM 40
#define YDIM 400
#define XDIM 400
#define KK 64
#define CC 64
#define TPB 256
#define TS 65  // shared tile row stride (floats) to dodge bank conflicts

__global__ __launch_bounds__(TPB) void grouper_kernel(
    const int* __restrict__ vox,     // [N,Z,Y,X]
    const int* __restrict__ gpos,    // [G,4] (n,z,y,x)
    const float* __restrict__ feat,  // [M,C]
    const int* __restrict__ off,     // [K,4] (0, oz, oy, ox) per reference indexing
    float* __restrict__ out,
    int G)
{
    __shared__ int   s_idx[KK];
    __shared__ float s_tile[KK * TS];  // tile[k][c]
    __shared__ int   s_cnt;

    const int g = blockIdx.x;
    const int t = threadIdx.x;

    if (t == 0) s_cnt = 0;
    __syncthreads();

    // ---- Phase 1: 64 voxel lookups for this grid position ----
    if (t < KK) {
        const int gn = gpos[g * 4 + 0];
        const int gz = gpos[g * 4 + 1];
        const int gy = gpos[g * 4 + 2];
        const int gx = gpos[g * 4 + 3];
        const int oz = off[t * 4 + 1];
        const int oy = off[t * 4 + 2];
        const int ox = off[t * 4 + 3];
        int z = min(max(gz + oz, 0), ZDIM - 1);
        int y = min(max(gy + oy, 0), YDIM - 1);
        int x = min(max(gx + ox, 0), XDIM - 1);
        int idx = vox[((gn * ZDIM + z) * YDIM + y) * XDIM + x];
        s_idx[t] = idx;
        if (idx >= 0) atomicAdd(&s_cnt, 1);
    }
    __syncthreads();

    // ---- Phase 2: gather feature rows (coalesced float4 reads) into tile[k][c] ----
    const float4* feat4 = reinterpret_cast<const float4*>(feat);
#pragma unroll
    for (int i = 0; i < 4; i++) {
        const int job = t + TPB * i;        // 0..1023
        const int k   = job >> 4;           // 0..63
        const int cq  = job & 15;           // float4 index within row
        const int idx = s_idx[k];
        float4 v = make_float4(0.f, 0.f, 0.f, 0.f);
        if (idx >= 0) v = feat4[(size_t)idx * (CC / 4) + cq];
        float* dst = &s_tile[k * TS + cq * 4];
        dst[0] = v.x; dst[1] = v.y; dst[2] = v.z; dst[3] = v.w;
    }
    __syncthreads();

    // ---- Phase 3: transposed write-out, float4 along k (coalesced stores) ----
    const size_t GK = (size_t)G * KK;
#pragma unroll
    for (int i = 0; i < 4; i++) {
        const int job = t + TPB * i;        // 0..1023
        const int c   = job >> 4;           // 0..63
        const int kq  = job & 15;
        float4 v;
        v.x = s_tile[(kq * 4 + 0) * TS + c];
        v.y = s_tile[(kq * 4 + 1) * TS + c];
        v.z = s_tile[(kq * 4 + 2) * TS + c];
        v.w = s_tile[(kq * 4 + 3) * TS + c];
        *reinterpret_cast<float4*>(out + (size_t)c * GK + (size_t)g * KK + kq * 4) = v;
    }

    // ---- gpf: pos is integer so frac = 0; gpf[ch,g,k] = offset[k][ch] ----
    {
        float* out_gpf = out + (size_t)CC * GK;
        const int ch = t >> 6;              // 0..3
        const int k  = t & 63;
        out_gpf[(size_t)ch * GK + (size_t)g * KK + k] = (float)off[k * 4 + ch];
    }

    // ---- empty mask ----
    if (t == 0) {
        float* out_mask = out + (size_t)CC * GK + (size_t)4 * GK;
        out_mask[g] = (s_cnt == 0) ? 1.0f : 0.0f;
    }
}

extern "C" void kernel_launch(void* const* d_in, const int* in_sizes, int n_in,
                              void* d_out, int out_size) {
    const int*   vox  = (const int*)d_in[0];
    const int*   gpos = (const int*)d_in[1];
    const float* feat = (const float*)d_in[2];
    const int*   off  = (const int*)d_in[3];
    float* out = (float*)d_out;

    const int G = in_sizes[1] / 4;
    grouper_kernel<<<G, TPB>>>(vox, gpos, feat, off, out, G);
}

// round 2
// speedup vs baseline: 1.0368x; 1.0368x over previous
#include <cuda_runtime.h>

// TorchGrouper: voxel-neighborhood feature gather + transpose.
// Output layout (float32): [C*G*K] sampled_features [C,G,K],
// then [4*G*K] gpf, then [G] empty_mask (1.0/0.0).
//
// Round-2 structure: BG=2 grid positions per block.
//  - Phase 1: 128 threads do 128 voxel lookups (2x MLP vs round 1)
//  - Phase 2: fill two 64x64 tiles, 8 independent float4 gathers/thread
//  - Phase 3: drain both tiles, 8 independent float4 streaming stores/thread
//  - 2 syncs per 2 g (was 2 per g); ballot-based empty mask (no atomics)

#define ZDIM 40
#define YDIM 400
#define XDIM 400
#define KK 64
#define CC 64
#define TPB 256
#define BG  2
#define TS  65  // tile row stride (floats) -> ~2-way max bank conflict

__global__ __launch_bounds__(TPB) void grouper_kernel(
    const int* __restrict__ vox,     // [N,Z,Y,X]
    const int* __restrict__ gpos,    // [G,4] (n,z,y,x)
    const float* __restrict__ feat,  // [M,C]
    const int* __restrict__ off,     // [K,4] (0, oz, oy, ox)
    float* __restrict__ out,
    int G)
{
    __shared__ int      s_idx[BG][KK];
    __shared__ float    s_tile[BG][KK * TS];
    __shared__ unsigned s_ball[BG * 2];   // one ballot word per 32 k's

    const int g0 = blockIdx.x * BG;
    const int t  = threadIdx.x;

    // ---- Phase 1: BG*64 voxel lookups ----
    if (t < BG * KK) {
        const int gi = t >> 6;
        const int k  = t & 63;
        const int4 gp = reinterpret_cast<const int4*>(gpos)[g0 + gi];
        const int4 of = reinterpret_cast<const int4*>(off)[k];
        int z = min(max(gp.y + of.y, 0), ZDIM - 1);
        int y = min(max(gp.z + of.z, 0), YDIM - 1);
        int x = min(max(gp.w + of.w, 0), XDIM - 1);
        int idx = __ldcs(&vox[((gp.x * ZDIM + z) * YDIM + y) * XDIM + x]);
        s_idx[gi][k] = idx;
        unsigned m = __ballot_sync(0xffffffffu, idx >= 0);
        if ((t & 31) == 0) s_ball[t >> 5] = m;
    }
    __syncthreads();

    // ---- Phase 2: gather feature rows into tiles [k][c] ----
    const float4* feat4 = reinterpret_cast<const float4*>(feat);
#pragma unroll
    for (int i = 0; i < (BG * KK * 16) / TPB; i++) {   // 8 iters
        const int job = t + TPB * i;
        const int gi  = job >> 10;
        const int k   = (job >> 4) & 63;
        const int cq  = job & 15;
        const int idx = s_idx[gi][k];
        float4 v = make_float4(0.f, 0.f, 0.f, 0.f);
        if (idx >= 0) v = feat4[(size_t)idx * (CC / 4) + cq];
        float* dst = &s_tile[gi][k * TS + cq * 4];
        dst[0] = v.x; dst[1] = v.y; dst[2] = v.z; dst[3] = v.w;
    }
    __syncthreads();

    // ---- Phase 3: transposed streaming write-out, float4 along k ----
    const size_t GK = (size_t)G * KK;
#pragma unroll
    for (int i = 0; i < (BG * CC * 16) / TPB; i++) {   // 8 iters
        const int job = t + TPB * i;
        const int gi  = job >> 10;
        const int c   = (job >> 4) & 63;
        const int kq  = job & 15;
        float4 v;
        v.x = s_tile[gi][(kq * 4 + 0) * TS + c];
        v.y = s_tile[gi][(kq * 4 + 1) * TS + c];
        v.z = s_tile[gi][(kq * 4 + 2) * TS + c];
        v.w = s_tile[gi][(kq * 4 + 3) * TS + c];
        __stcs(reinterpret_cast<float4*>(
                   out + (size_t)c * GK + (size_t)(g0 + gi) * KK + kq * 4), v);
    }

    // ---- gpf: positions are integers => frac = 0; gpf[ch,g,k] = offset[k][ch] ----
    {
        float* out_gpf = out + (size_t)CC * GK;
#pragma unroll
        for (int i = 0; i < (BG * 4 * KK) / TPB; i++) {  // 2 iters
            const int job = t + TPB * i;                 // 0..511
            const int gi  = job >> 8;
            const int ch  = (job >> 6) & 3;
            const int k   = job & 63;
            out_gpf[(size_t)ch * GK + (size_t)(g0 + gi) * KK + k] = (float)off[k * 4 + ch];
        }
    }

    // ---- empty mask ----
    if (t < BG) {
        float* out_mask = out + (size_t)(CC + 4) * GK;
        out_mask[g0 + t] = ((s_ball[2 * t] | s_ball[2 * t + 1]) == 0u) ? 1.0f : 0.0f;
    }
}

extern "C" void kernel_launch(void* const* d_in, const int* in_sizes, int n_in,
                              void* d_out, int out_size) {
    const int*   vox  = (const int*)d_in[0];
    const int*   gpos = (const int*)d_in[1];
    const float* feat = (const float*)d_in[2];
    const int*   off  = (const int*)d_in[3];
    float* out = (float*)d_out;

    const int G = in_sizes[1] / 4;     // 30000 (even; BG=2 divides)
    grouper_kernel<<<G / BG, TPB>>>(vox, gpos, feat, off, out, G);
}